// round 9
// baseline (speedup 1.0000x reference)
#include <cuda_runtime.h>
#include <cstdint>

// out[tok, :] = sum_{l=0..7} weight[l, x[tok, l], :]
//   x:      16384 tokens x 8 int32 indices
//   weight: (8, 1024, 1024) f32, 32 MB (L2-resident)
//   out:    16384 x 1024 f32
//
// L1-bypass design: per-token CTA stages its 8 weight rows (8 x 4KB) into
// SMEM via cp.async.bulk (TMA linear copy, L2->SMEM direct — no L1 fill/read
// traffic), then reduces from SMEM and streams the result out.

static constexpr int NTOK      = 8 * 2048;  // 16384
static constexpr int K         = 1024;
static constexpr int D4        = 1024 / 4;  // 256 float4 per row
static constexpr int L         = 8;
static constexpr int ROW_BYTES = 4096;      // one weight row

__global__ __launch_bounds__(256, 6)
void multi_embed_kernel(const int4* __restrict__ x4,
                        const float4* __restrict__ w,
                        float4* __restrict__ out)
{
    __shared__ alignas(128) float4 tile[L][D4];   // 32 KB
    __shared__ alignas(8) uint64_t mbar;

    const int tok = blockIdx.x;
    const int tid = threadIdx.x;

    uint32_t smem_base;
    asm("{ .reg .u64 t; cvta.to.shared.u64 t, %1; cvt.u32.u64 %0, t; }"
        : "=r"(smem_base) : "l"(&tile[0][0]));
    uint32_t mbar_addr;
    asm("{ .reg .u64 t; cvta.to.shared.u64 t, %1; cvt.u32.u64 %0, t; }"
        : "=r"(mbar_addr) : "l"(&mbar));

    if (tid == 0) {
        asm volatile("mbarrier.init.shared.b64 [%0], 1;"
                     :: "r"(mbar_addr) : "memory");
    }
    __syncthreads();

    if (tid == 0) {
        const int4 iA = __ldg(x4 + tok * 2);       // l = 0..3
        const int4 iB = __ldg(x4 + tok * 2 + 1);   // l = 4..7

        asm volatile("mbarrier.arrive.expect_tx.shared.b64 _, [%0], %1;"
                     :: "r"(mbar_addr), "r"((uint32_t)(L * ROW_BYTES))
                     : "memory");

        int rows[L];
        rows[0] = 0 * K + iA.x;  rows[1] = 1 * K + iA.y;
        rows[2] = 2 * K + iA.z;  rows[3] = 3 * K + iA.w;
        rows[4] = 4 * K + iB.x;  rows[5] = 5 * K + iB.y;
        rows[6] = 6 * K + iB.z;  rows[7] = 7 * K + iB.w;

#pragma unroll
        for (int l = 0; l < L; ++l) {
            const float4* src = w + (size_t)rows[l] * D4;
            uint32_t dst = smem_base + l * ROW_BYTES;
            asm volatile(
                "cp.async.bulk.shared::cta.global.mbarrier::complete_tx::bytes "
                "[%0], [%1], %2, [%3];"
                :: "r"(dst), "l"(src), "r"((uint32_t)ROW_BYTES), "r"(mbar_addr)
                : "memory");
        }
    }

    // All threads wait for the 32 KB to land (acquire: orders the LDS reads).
    {
        uint32_t done;
        asm volatile(
            "{\n\t"
            ".reg .pred p;\n\t"
            "mbarrier.try_wait.parity.acquire.cta.shared::cta.b64 p, [%1], 0;\n\t"
            "selp.b32 %0, 1, 0, p;\n\t"
            "}"
            : "=r"(done) : "r"(mbar_addr) : "memory");
        if (!done) {
            asm volatile(
                "{\n\t"
                ".reg .pred P1;\n\t"
                "WL_%=:\n\t"
                "mbarrier.try_wait.parity.acquire.cta.shared::cta.b64 P1, [%0], 0, 0x989680;\n\t"
                "@P1 bra.uni WD_%=;\n\t"
                "bra.uni WL_%=;\n\t"
                "WD_%=:\n\t"
                "}"
                :: "r"(mbar_addr) : "memory");
        }
    }

    // Reduce 8 rows from SMEM (conflict-free: consecutive 16B per lane).
    float4 acc = tile[0][tid];
#pragma unroll
    for (int l = 1; l < L; ++l) {
        float4 v = tile[l][tid];
        acc.x += v.x; acc.y += v.y; acc.z += v.z; acc.w += v.w;
    }

    // Streaming store: evict-first, don't displace weight lines in L2.
    float4* dst = out + (size_t)tok * D4 + tid;
    asm volatile("st.global.cs.v4.f32 [%0], {%1, %2, %3, %4};"
                 :: "l"(dst), "f"(acc.x), "f"(acc.y), "f"(acc.z), "f"(acc.w)
                 : "memory");
}

extern "C" void kernel_launch(void* const* d_in, const int* in_sizes, int n_in,
                              void* d_out, int out_size)
{
    const int4*   x = (const int4*)d_in[0];
    const float4* w = (const float4*)d_in[1];
    float4*       o = (float4*)d_out;

    multi_embed_kernel<<<NTOK, 256>>>(x, w, o);
}

// round 10
// speedup vs baseline: 1.1976x; 1.1976x over previous
#include <cuda_runtime.h>
#include <cstdint>

// out[tok, :] = sum_{l=0..7} weight[l, x[tok, l], :]
//   x:      16384 tokens x 8 int32 indices
//   weight: (8, 1024, 1024) f32, 32 MB (L2-resident)
//   out:    16384 x 1024 f32
//
// R6 winner body, but 2 consecutive tokens per 512-thread CTA:
// halves CTA-scheduling churn while keeping per-thread work and
// consecutive-token cache locality identical.

static constexpr int NTOK = 8 * 2048;   // 16384
static constexpr int K    = 1024;
static constexpr int D4   = 1024 / 4;   // 256 float4 per row

__device__ __forceinline__ float4 ldg_evict_last(const float4* p)
{
    float4 v;
    asm volatile("ld.global.nc.L1::evict_last.v4.f32 {%0, %1, %2, %3}, [%4];"
                 : "=f"(v.x), "=f"(v.y), "=f"(v.z), "=f"(v.w)
                 : "l"(p));
    return v;
}

__global__ __launch_bounds__(512, 4)
void multi_embed_kernel(const int4* __restrict__ x4,
                        const float4* __restrict__ w,
                        float4* __restrict__ out)
{
    const int tid = threadIdx.x;
    const int tok = blockIdx.x * 2 + (tid >> 8);   // token A: tid 0-255, B: 256-511
    const int col = tid & 255;

    // All 8 indices via two uniform 16B loads (broadcast within each half).
    const int4 iA = __ldg(x4 + tok * 2);       // l = 0..3
    const int4 iB = __ldg(x4 + tok * 2 + 1);   // l = 4..7

    const float4* wt = w + col;

    // 8 independent LDG.128 front-batched (MLP=8), evict_last in L1.
    float4 a0 = ldg_evict_last(wt + (size_t)(0 * K + iA.x) * D4);
    float4 a1 = ldg_evict_last(wt + (size_t)(1 * K + iA.y) * D4);
    float4 a2 = ldg_evict_last(wt + (size_t)(2 * K + iA.z) * D4);
    float4 a3 = ldg_evict_last(wt + (size_t)(3 * K + iA.w) * D4);
    float4 b0 = ldg_evict_last(wt + (size_t)(4 * K + iB.x) * D4);
    float4 b1 = ldg_evict_last(wt + (size_t)(5 * K + iB.y) * D4);
    float4 b2 = ldg_evict_last(wt + (size_t)(6 * K + iB.z) * D4);
    float4 b3 = ldg_evict_last(wt + (size_t)(7 * K + iB.w) * D4);

    float4 acc;
    acc.x = (a0.x + a1.x) + (a2.x + a3.x);
    acc.y = (a0.y + a1.y) + (a2.y + a3.y);
    acc.z = (a0.z + a1.z) + (a2.z + a3.z);
    acc.w = (a0.w + a1.w) + (a2.w + a3.w);

    acc.x += (b0.x + b1.x) + (b2.x + b3.x);
    acc.y += (b0.y + b1.y) + (b2.y + b3.y);
    acc.z += (b0.z + b1.z) + (b2.z + b3.z);
    acc.w += (b0.w + b1.w) + (b2.w + b3.w);

    // Streaming store: evict-first, don't displace weight lines.
    float4* dst = out + (size_t)tok * D4 + col;
    asm volatile("st.global.cs.v4.f32 [%0], {%1, %2, %3, %4};"
                 :: "l"(dst), "f"(acc.x), "f"(acc.y), "f"(acc.z), "f"(acc.w)
                 : "memory");
}

extern "C" void kernel_launch(void* const* d_in, const int* in_sizes, int n_in,
                              void* d_out, int out_size)
{
    const int4*   x = (const int4*)d_in[0];
    const float4* w = (const float4*)d_in[1];
    float4*       o = (float4*)d_out;

    multi_embed_kernel<<<NTOK / 2, 512>>>(x, w, o);
}